// round 1
// baseline (speedup 1.0000x reference)
#include <cuda_runtime.h>

#define V_     10000
#define VPAD   10240
#define E_     128
#define NTOK   2048
#define NR     8

// ---------------- scratch (device globals; no allocations) ----------------
__device__ float         g_base[(size_t)NTOK * VPAD];   // base scores, padded rows
__device__ unsigned char g_cls [(size_t)NTOK * VPAD];   // relation class 0..8 per (t,v)
__device__ int           g_Mbits[NTOK * NR];            // per-(t,r) max(0, masked base) as float bits
__device__ float         g_colsum[E_];                  // column sums of W
__device__ float         g_part[40 * E_];               // colsum partials

// ---------------- init ----------------
__global__ void k_init() {
    int i = blockIdx.x * blockDim.x + threadIdx.x;
    if (i < NTOK * NR) g_Mbits[i] = 0;    // 0 bits == 0.0f (the softmax floor)
}

// ---------------- column sums of W (deterministic 2-stage) ----------------
__global__ void k_colsum1(const float* __restrict__ W) {
    int b = blockIdx.x, col = threadIdx.x;
    float s = 0.f;
    int v0 = b * 250;
    for (int v = v0; v < v0 + 250; v++) s += W[v * E_ + col];
    g_part[b * E_ + col] = s;
}
__global__ void k_colsum2() {
    int col = threadIdx.x;
    float s = 0.f;
    for (int b = 0; b < 40; b++) s += g_part[b * E_ + col];
    g_colsum[col] = s;
}

// ---------------- base GEMM + classification + per-(t,r) max ----------------
#define BT 32
#define BV 128
#define KC 32

__global__ __launch_bounds__(256) void k_base(
    const int*   __restrict__ src,
    const float* __restrict__ X,      // src_embed [NTOK, E]
    const float* __restrict__ W,      // embed_weight [V, E]
    const float* __restrict__ edge,   // [V, V]
    const int*   __restrict__ rel)    // [V, V]
{
    __shared__ float Xs[KC][BT + 4];
    __shared__ float Ws[KC][BV + 4];
    __shared__ int   ssm[BT];
    __shared__ int   mx[BT][NR];

    int tid  = threadIdx.x;
    int vblk = blockIdx.x * BV;
    int tblk = blockIdx.y * BT;

    if (tid < BT) ssm[tid] = src[tblk + tid];
    ((int*)mx)[tid] = 0;   // BT*NR == 256 == blockDim

    float acc[4][4];
#pragma unroll
    for (int i = 0; i < 4; i++)
#pragma unroll
        for (int j = 0; j < 4; j++) acc[i][j] = 0.f;

    int ty = tid >> 5;   // token quad: tokens 4*ty..4*ty+3
    int tx = tid & 31;   // v quad:     v 4*tx..4*tx+3

    for (int kc = 0; kc < E_; kc += KC) {
        __syncthreads();
#pragma unroll
        for (int j = 0; j < 4; j++) {                // X chunk: 32x32, k-major
            int idx = tid + 256 * j;
            int t = idx >> 5, k = idx & 31;
            Xs[k][t] = X[(tblk + t) * E_ + kc + k];
        }
#pragma unroll
        for (int j = 0; j < 16; j++) {               // W chunk: 128x32, k-major
            int idx = tid + 256 * j;
            int v = idx >> 5, k = idx & 31;
            int gv = vblk + v;
            Ws[k][v] = (gv < V_) ? W[gv * E_ + kc + k] : 0.f;
        }
        __syncthreads();
#pragma unroll
        for (int kk = 0; kk < KC; kk++) {
            float4 a4 = *(const float4*)&Xs[kk][4 * ty];
            float4 b4 = *(const float4*)&Ws[kk][4 * tx];
            float av[4] = {a4.x, a4.y, a4.z, a4.w};
            float bv[4] = {b4.x, b4.y, b4.z, b4.w};
#pragma unroll
            for (int i = 0; i < 4; i++)
#pragma unroll
                for (int j = 0; j < 4; j++)
                    acc[i][j] += av[i] * bv[j];
        }
    }

    // epilogue: store base, classify, local max
    int v0 = vblk + 4 * tx;
#pragma unroll
    for (int i = 0; i < 4; i++) {
        int tl = 4 * ty + i;
        int t  = tblk + tl;
        float4 bb = make_float4(acc[i][0], acc[i][1], acc[i][2], acc[i][3]);
        *(float4*)&g_base[(size_t)t * VPAD + v0] = bb;   // pad region writes OK, never read
        if (v0 < V_) {
            long s = ssm[tl];
            int4   r4 = *(const int4*)  (rel  + s * (long)V_ + v0);
            float4 e4 = *(const float4*)(edge + s * (long)V_ + v0);
            uchar4 c;
            c.x = (r4.x >= 1 && r4.x <= 8 && e4.x > 0.f) ? (unsigned char)r4.x : 0;
            c.y = (r4.y >= 1 && r4.y <= 8 && e4.y > 0.f) ? (unsigned char)r4.y : 0;
            c.z = (r4.z >= 1 && r4.z <= 8 && e4.z > 0.f) ? (unsigned char)r4.z : 0;
            c.w = (r4.w >= 1 && r4.w <= 8 && e4.w > 0.f) ? (unsigned char)r4.w : 0;
            *(uchar4*)&g_cls[(size_t)t * VPAD + v0] = c;
            if (c.x && bb.x > 0.f) atomicMax(&mx[tl][c.x - 1], __float_as_int(bb.x));
            if (c.y && bb.y > 0.f) atomicMax(&mx[tl][c.y - 1], __float_as_int(bb.y));
            if (c.z && bb.z > 0.f) atomicMax(&mx[tl][c.z - 1], __float_as_int(bb.z));
            if (c.w && bb.w > 0.f) atomicMax(&mx[tl][c.w - 1], __float_as_int(bb.w));
        }
    }
    __syncthreads();
    {
        int tl = tid >> 3, r = tid & 7;
        int m = mx[tl][r];
        if (m) atomicMax(&g_Mbits[(tblk + tl) * NR + r], m);
    }
}

// ---------------- segmented accumulation + softmaxes + output ----------------
#define TCTA 8
#define VT   64

__global__ __launch_bounds__(256) void k_accum(
    const float* __restrict__ W,     // embed_weight
    const float* __restrict__ X,     // src_embed
    float*       __restrict__ out)
{
    __shared__ float Ws[VT][E_];          // 32 KB
    __shared__ float a_sm[TCTA][VT];      // 2 KB
    __shared__ float wM[TCTA][NR];
    __shared__ float wbg[TCTA][NR];

    int tid  = threadIdx.x;
    int w    = tid >> 5;
    int lane = tid & 31;
    int t    = blockIdx.x * TCTA + w;

    if (lane < NR) {
        float M = __int_as_float(g_Mbits[t * NR + lane]);  // >= 0 by construction
        wM[w][lane]  = M;
        wbg[w][lane] = __expf(-M);
    }

    float4 acc[NR];
    float  za[NR];
#pragma unroll
    for (int r = 0; r < NR; r++) {
        acc[r] = make_float4(0.f, 0.f, 0.f, 0.f);
        za[r]  = 0.f;
    }

    for (int vblk = 0; vblk < V_; vblk += VT) {
        __syncthreads();
        // cooperative W tile load: VT x E floats, 8 float4 per thread
#pragma unroll
        for (int j = 0; j < 8; j++) {
            int p  = tid + 256 * j;       // float4 index
            int v  = p >> 5;              // 32 float4 per 128-float row
            int e4 = (p & 31) << 2;
            float4 val = (vblk + v < V_) ? *(const float4*)&W[(vblk + v) * E_ + e4]
                                         : make_float4(0.f, 0.f, 0.f, 0.f);
            *(float4*)&Ws[v][e4] = val;
        }
        __syncthreads();

        // phase 1: per-lane a-values + per-relation 64-bit ballot masks
        unsigned long long mask[NR];
#pragma unroll
        for (int r = 0; r < NR; r++) mask[r] = 0ull;

#pragma unroll
        for (int s = 0; s < 2; s++) {
            int vl = s * 32 + lane;
            int v  = vblk + vl;
            float a = 0.f;
            int   c = 0;
            if (v < V_) {
                c = g_cls[(size_t)t * VPAD + v];
                if (c) {
                    float b = g_base[(size_t)t * VPAD + v];
                    a = __expf(b - wM[w][c - 1]) - wbg[w][c - 1];
                }
            }
            a_sm[w][vl] = a;
#pragma unroll
            for (int r = 1; r <= NR; r++) {
                unsigned bal = __ballot_sync(0xFFFFFFFFu, c == r);
                mask[r - 1] |= (unsigned long long)bal << (32 * s);
            }
        }
        __syncwarp();

        // phase 2: register accumulation per relation, warp-uniform bit loop
#pragma unroll
        for (int r = 0; r < NR; r++) {
            unsigned long long m = mask[r];
            while (m) {
                int i = __ffsll((long long)m) - 1;
                m &= m - 1;
                float a   = a_sm[w][i];
                float4 wv = *(const float4*)&Ws[i][lane * 4];
                acc[r].x += a * wv.x;
                acc[r].y += a * wv.y;
                acc[r].z += a * wv.z;
                acc[r].w += a * wv.w;
                za[r] += a;
            }
        }
    }

    // finalize: ce_r, scores, 8-way softmax, output — all in-warp
    float4 sw = *(const float4*)&g_colsum[lane * 4];
    float4 x4 = *(const float4*)&X[t * E_ + lane * 4];
    float4 ce[NR];
    float  sc[NR];
#pragma unroll
    for (int r = 0; r < NR; r++) {
        float bg = wbg[w][r];
        float Z  = (float)V_ * bg + za[r];
        ce[r].x = (acc[r].x + bg * sw.x) / Z;
        ce[r].y = (acc[r].y + bg * sw.y) / Z;
        ce[r].z = (acc[r].z + bg * sw.z) / Z;
        ce[r].w = (acc[r].w + bg * sw.w) / Z;
        float p = x4.x * ce[r].x + x4.y * ce[r].y + x4.z * ce[r].z + x4.w * ce[r].w;
#pragma unroll
        for (int o = 16; o; o >>= 1) p += __shfl_xor_sync(0xFFFFFFFFu, p, o);
        sc[r] = p;
    }
    float mxs = sc[0];
#pragma unroll
    for (int r = 1; r < NR; r++) mxs = fmaxf(mxs, sc[r]);
    float es[NR], ssum = 0.f;
#pragma unroll
    for (int r = 0; r < NR; r++) { es[r] = __expf(sc[r] - mxs); ssum += es[r]; }
    float inv = 1.f / ssum;
    float4 o4 = make_float4(0.f, 0.f, 0.f, 0.f);
#pragma unroll
    for (int r = 0; r < NR; r++) {
        float wt = es[r] * inv;
        o4.x += wt * ce[r].x;
        o4.y += wt * ce[r].y;
        o4.z += wt * ce[r].z;
        o4.w += wt * ce[r].w;
    }
    *(float4*)&out[t * E_ + lane * 4] = o4;
}

// ---------------- launch ----------------
extern "C" void kernel_launch(void* const* d_in, const int* in_sizes, int n_in,
                              void* d_out, int out_size) {
    const int*   src  = (const int*)  d_in[0];
    const float* X    = (const float*)d_in[1];   // src_embed
    const float* W    = (const float*)d_in[2];   // embed_weight
    const float* edge = (const float*)d_in[3];
    const int*   rel  = (const int*)  d_in[4];
    float* out = (float*)d_out;

    k_init<<<64, 256>>>();
    k_colsum1<<<40, 128>>>(W);
    k_colsum2<<<1, 128>>>();

    dim3 gb((V_ + BV - 1) / BV, NTOK / BT);   // 79 x 64
    k_base<<<gb, 256>>>(src, X, W, edge, rel);

    k_accum<<<NTOK / TCTA, 256>>>(W, X, out);
    (void)in_sizes; (void)n_in; (void)out_size;
}

// round 2
// speedup vs baseline: 1.6543x; 1.6543x over previous
#include <cuda_runtime.h>

#define V_     10000
#define VPAD   10240
#define E_     128
#define NTOK   2048
#define NR     8

// ---------------- scratch (device globals; no allocations) ----------------
__device__ float         g_base[(size_t)NTOK * VPAD];   // base scores, padded rows
__device__ unsigned char g_cls [(size_t)NTOK * VPAD];   // relation class 0..8 per (t,v); pad stays 0
__device__ int           g_Mbits[NTOK * NR];            // per-(t,r) max(0, masked base) as float bits
__device__ float         g_colsum[E_];                  // column sums of W
__device__ float         g_part[40 * E_];               // colsum partials
__device__ float         g_stats[NTOK * 25];            // per token: K1[8], K2[8], M[8], beta
__device__ float         g_psum[2][(size_t)NTOK * E_];  // K-split partial outputs

// ---------------- init ----------------
__global__ void k_init() {
    int i = blockIdx.x * blockDim.x + threadIdx.x;
    if (i < NTOK * NR) g_Mbits[i] = 0;    // 0 bits == 0.0f (the softmax floor)
}

// ---------------- column sums of W (deterministic 2-stage) ----------------
__global__ void k_colsum1(const float* __restrict__ W) {
    int b = blockIdx.x, col = threadIdx.x;
    float s = 0.f;
    int v0 = b * 250;
    for (int v = v0; v < v0 + 250; v++) s += W[v * E_ + col];
    g_part[b * E_ + col] = s;
}
__global__ void k_colsum2() {
    int col = threadIdx.x;
    float s = 0.f;
    for (int b = 0; b < 40; b++) s += g_part[b * E_ + col];
    g_colsum[col] = s;
}

// ---------------- base GEMM + classification + per-(t,r) max ----------------
#define BT 32
#define BV 128
#define KCB 32

__global__ __launch_bounds__(256) void k_base(
    const int*   __restrict__ src,
    const float* __restrict__ X,      // src_embed [NTOK, E]
    const float* __restrict__ W,      // embed_weight [V, E]
    const float* __restrict__ edge,   // [V, V]
    const int*   __restrict__ rel)    // [V, V]
{
    __shared__ float Xs[KCB][BT + 4];
    __shared__ float Ws[KCB][BV + 4];
    __shared__ int   ssm[BT];
    __shared__ int   mx[BT][NR];

    int tid  = threadIdx.x;
    int vblk = blockIdx.x * BV;
    int tblk = blockIdx.y * BT;

    if (tid < BT) ssm[tid] = src[tblk + tid];
    ((int*)mx)[tid] = 0;   // BT*NR == 256 == blockDim

    float acc[4][4];
#pragma unroll
    for (int i = 0; i < 4; i++)
#pragma unroll
        for (int j = 0; j < 4; j++) acc[i][j] = 0.f;

    int ty = tid >> 5;   // token quad
    int tx = tid & 31;   // v quad

    for (int kc = 0; kc < E_; kc += KCB) {
        __syncthreads();
#pragma unroll
        for (int j = 0; j < 4; j++) {
            int idx = tid + 256 * j;
            int t = idx >> 5, k = idx & 31;
            Xs[k][t] = X[(tblk + t) * E_ + kc + k];
        }
#pragma unroll
        for (int j = 0; j < 16; j++) {
            int idx = tid + 256 * j;
            int v = idx >> 5, k = idx & 31;
            int gv = vblk + v;
            Ws[k][v] = (gv < V_) ? W[gv * E_ + kc + k] : 0.f;
        }
        __syncthreads();
#pragma unroll
        for (int kk = 0; kk < KCB; kk++) {
            float4 a4 = *(const float4*)&Xs[kk][4 * ty];
            float4 b4 = *(const float4*)&Ws[kk][4 * tx];
            float av[4] = {a4.x, a4.y, a4.z, a4.w};
            float bv[4] = {b4.x, b4.y, b4.z, b4.w};
#pragma unroll
            for (int i = 0; i < 4; i++)
#pragma unroll
                for (int j = 0; j < 4; j++)
                    acc[i][j] += av[i] * bv[j];
        }
    }

    int v0 = vblk + 4 * tx;
#pragma unroll
    for (int i = 0; i < 4; i++) {
        int tl = 4 * ty + i;
        int t  = tblk + tl;
        float4 bb = make_float4(acc[i][0], acc[i][1], acc[i][2], acc[i][3]);
        *(float4*)&g_base[(size_t)t * VPAD + v0] = bb;
        if (v0 < V_) {
            long s = ssm[tl];
            int4   r4 = *(const int4*)  (rel  + s * (long)V_ + v0);
            float4 e4 = *(const float4*)(edge + s * (long)V_ + v0);
            uchar4 c;
            c.x = (r4.x >= 1 && r4.x <= 8 && e4.x > 0.f) ? (unsigned char)r4.x : 0;
            c.y = (r4.y >= 1 && r4.y <= 8 && e4.y > 0.f) ? (unsigned char)r4.y : 0;
            c.z = (r4.z >= 1 && r4.z <= 8 && e4.z > 0.f) ? (unsigned char)r4.z : 0;
            c.w = (r4.w >= 1 && r4.w <= 8 && e4.w > 0.f) ? (unsigned char)r4.w : 0;
            *(uchar4*)&g_cls[(size_t)t * VPAD + v0] = c;
            if (c.x && bb.x > 0.f) atomicMax(&mx[tl][c.x - 1], __float_as_int(bb.x));
            if (c.y && bb.y > 0.f) atomicMax(&mx[tl][c.y - 1], __float_as_int(bb.y));
            if (c.z && bb.z > 0.f) atomicMax(&mx[tl][c.z - 1], __float_as_int(bb.z));
            if (c.w && bb.w > 0.f) atomicMax(&mx[tl][c.w - 1], __float_as_int(bb.w));
        }
    }
    __syncthreads();
    {
        int tl = tid >> 3, r = tid & 7;
        int m = mx[tl][r];
        if (m) atomicMax(&g_Mbits[(tblk + tl) * NR + r], m);
    }
}

// ---------------- per-(t,r) softmax stats + mixture weights ----------------
__global__ __launch_bounds__(256) void k_stats() {
    int t   = blockIdx.x;
    int tid = threadIdx.x;
    __shared__ float Msm[NR], bgsm[NR];
    __shared__ float red[8][36];
    __shared__ float fin[36];

    if (tid < NR) {
        float M = __int_as_float(g_Mbits[t * NR + tid]);
        Msm[tid]  = M;
        bgsm[tid] = __expf(-M);
    }
    __syncthreads();

    float e[NR], d[NR], b[NR], n[NR];
#pragma unroll
    for (int r = 0; r < NR; r++) { e[r] = 0.f; d[r] = 0.f; b[r] = 0.f; n[r] = 0.f; }
    float B = 0.f;

    const float*         baseRow = g_base + (size_t)t * VPAD;
    const unsigned char* clsRow  = g_cls  + (size_t)t * VPAD;

    for (int i = tid; i < V_ / 4; i += 256) {
        float4 b4 = *(const float4*)(baseRow + 4 * i);
        uchar4 c4 = *(const uchar4*)(clsRow + 4 * i);
        float bs[4] = {b4.x, b4.y, b4.z, b4.w};
        int   cc[4] = {c4.x, c4.y, c4.z, c4.w};
#pragma unroll
        for (int j = 0; j < 4; j++) {
            float v = bs[j];
            int   c = cc[j];
            B += v;
            if (c) {
                float p = __expf(v - Msm[c - 1]);
#pragma unroll
                for (int r = 0; r < NR; r++)
                    if (c == r + 1) { e[r] += p; d[r] = fmaf(p, v, d[r]); b[r] += v; n[r] += 1.f; }
            }
        }
    }

#pragma unroll
    for (int o = 16; o; o >>= 1) {
        B += __shfl_xor_sync(0xFFFFFFFFu, B, o);
#pragma unroll
        for (int r = 0; r < NR; r++) {
            e[r] += __shfl_xor_sync(0xFFFFFFFFu, e[r], o);
            d[r] += __shfl_xor_sync(0xFFFFFFFFu, d[r], o);
            b[r] += __shfl_xor_sync(0xFFFFFFFFu, b[r], o);
            n[r] += __shfl_xor_sync(0xFFFFFFFFu, n[r], o);
        }
    }
    int w = tid >> 5, lane = tid & 31;
    if (lane == 0) {
#pragma unroll
        for (int r = 0; r < NR; r++) {
            red[w][r]      = e[r];
            red[w][8 + r]  = d[r];
            red[w][16 + r] = b[r];
            red[w][24 + r] = n[r];
        }
        red[w][32] = B;
    }
    __syncthreads();
    if (tid < 33) {
        float s = 0.f;
#pragma unroll
        for (int k = 0; k < 8; k++) s += red[k][tid];
        fin[tid] = s;
    }
    __syncthreads();
    if (tid == 0) {
        float sc[NR], Zv[NR];
        float Bt = fin[32];
#pragma unroll
        for (int r = 0; r < NR; r++) {
            float bg = bgsm[r];
            float Z  = ((float)V_ - fin[24 + r]) * bg + fin[r];
            Zv[r] = Z;
            sc[r] = (fin[8 + r] + bg * (Bt - fin[16 + r])) / Z;
        }
        float mx = sc[0];
#pragma unroll
        for (int r = 1; r < NR; r++) mx = fmaxf(mx, sc[r]);
        float es[NR], ss = 0.f;
#pragma unroll
        for (int r = 0; r < NR; r++) { es[r] = __expf(sc[r] - mx); ss += es[r]; }
        float inv = 1.f / ss;
        float beta = 0.f;
        float* st = g_stats + t * 25;
#pragma unroll
        for (int r = 0; r < NR; r++) {
            float wgt = es[r] * inv;
            float K1 = wgt / Zv[r];
            float K2 = K1 * bgsm[r];
            st[r]      = K1;
            st[8 + r]  = K2;
            st[16 + r] = Msm[r];
            beta += K2;
        }
        st[24] = beta;
    }
}

// ---------------- final dense GEMM with on-the-fly gamma ----------------
#define KCF   32
#define BMF   32
#define KHALF 5120

__device__ __forceinline__ void fma2(unsigned long long& acc,
                                     unsigned long long a, unsigned long long bb) {
    asm("fma.rn.f32x2 %0, %1, %2, %0;" : "+l"(acc) : "l"(a), "l"(bb));
}

__global__ __launch_bounds__(256) void k_final(const float* __restrict__ W) {
    __shared__ float Ws[KCF][E_];          // 16 KB
    __shared__ float As2[KCF][2 * BMF];    // 8 KB, gamma duplicated pairs
    __shared__ float K1s[BMF][NR], K2s[BMF][NR], Ms[BMF][NR];

    int tid  = threadIdx.x;
    int t0   = blockIdx.x * BMF;
    int half = blockIdx.y;
    int k0   = half * KHALF;

    {   // per-token stats: 32 tokens x 8 relations == 256 threads
        int tok = tid >> 3, r = tid & 7;
        const float* st = g_stats + (t0 + tok) * 25;
        K1s[tok][r] = st[r];
        K2s[tok][r] = st[8 + r];
        Ms[tok][r]  = st[16 + r];
    }

    unsigned long long acc[4][2];
#pragma unroll
    for (int i = 0; i < 4; i++) { acc[i][0] = 0ull; acc[i][1] = 0ull; }

    int tx = tid & 31, ty = tid >> 5;

    for (int kc = k0; kc < k0 + KHALF; kc += KCF) {
        __syncthreads();
        // W tile: 32 x 128 floats
#pragma unroll
        for (int j = 0; j < 4; j++) {
            int p  = tid + 256 * j;     // float4 index
            int v  = p >> 5;
            int e4 = (p & 31) * 4;
            int gv = kc + v;
            float4 val = (gv < V_) ? *(const float4*)&W[(size_t)gv * E_ + e4]
                                   : make_float4(0.f, 0.f, 0.f, 0.f);
            *(float4*)&Ws[v][e4] = val;
        }
        // A tile: gamma for 32 tokens x 32 v, duplicated as f32x2 pairs
        {
            int tok = tid >> 3;
            int v4  = (tid & 7) * 4;
            size_t off = (size_t)(t0 + tok) * VPAD + kc + v4;
            float4 b4 = *(const float4*)(g_base + off);
            uchar4 c4 = *(const uchar4*)(g_cls + off);
            float bs[4] = {b4.x, b4.y, b4.z, b4.w};
            int   cc[4] = {c4.x, c4.y, c4.z, c4.w};
#pragma unroll
            for (int j = 0; j < 4; j++) {
                float g = 0.f;
                int c = cc[j];
                if (c) g = K1s[tok][c - 1] * __expf(bs[j] - Ms[tok][c - 1]) - K2s[tok][c - 1];
                *(float2*)&As2[v4 + j][2 * tok] = make_float2(g, g);
            }
        }
        __syncthreads();
#pragma unroll 4
        for (int kk = 0; kk < KCF; kk++) {
            ulonglong2 w2  = *(const ulonglong2*)&Ws[kk][4 * tx];
            ulonglong2 a01 = *(const ulonglong2*)&As2[kk][8 * ty];
            ulonglong2 a23 = *(const ulonglong2*)&As2[kk][8 * ty + 4];
            fma2(acc[0][0], a01.x, w2.x); fma2(acc[0][1], a01.x, w2.y);
            fma2(acc[1][0], a01.y, w2.x); fma2(acc[1][1], a01.y, w2.y);
            fma2(acc[2][0], a23.x, w2.x); fma2(acc[2][1], a23.x, w2.y);
            fma2(acc[3][0], a23.y, w2.x); fma2(acc[3][1], a23.y, w2.y);
        }
    }

    float* ps = g_psum[half];
#pragma unroll
    for (int i = 0; i < 4; i++) {
        int t = t0 + 4 * ty + i;
        float2 lo = *(float2*)&acc[i][0];
        float2 hi = *(float2*)&acc[i][1];
        *(float4*)&ps[(size_t)t * E_ + 4 * tx] = make_float4(lo.x, lo.y, hi.x, hi.y);
    }
}

// ---------------- combine K-split partials + background term ----------------
__global__ void k_combine(float* __restrict__ out) {
    int i  = blockIdx.x * 256 + threadIdx.x;  // float4 index; 65536 total
    int t  = i >> 5;
    int c4 = (i & 31) * 4;
    size_t off = (size_t)t * E_ + c4;
    float4 a = *(const float4*)&g_psum[0][off];
    float4 b = *(const float4*)&g_psum[1][off];
    float  beta = g_stats[t * 25 + 24];
    float4 cs = *(const float4*)&g_colsum[c4];
    float4 o;
    o.x = a.x + b.x + beta * cs.x;
    o.y = a.y + b.y + beta * cs.y;
    o.z = a.z + b.z + beta * cs.z;
    o.w = a.w + b.w + beta * cs.w;
    *(float4*)&out[off] = o;
}

// ---------------- launch ----------------
extern "C" void kernel_launch(void* const* d_in, const int* in_sizes, int n_in,
                              void* d_out, int out_size) {
    const int*   src  = (const int*)  d_in[0];
    const float* X    = (const float*)d_in[1];
    const float* W    = (const float*)d_in[2];
    const float* edge = (const float*)d_in[3];
    const int*   rel  = (const int*)  d_in[4];
    float* out = (float*)d_out;

    k_init<<<64, 256>>>();
    k_colsum1<<<40, 128>>>(W);
    k_colsum2<<<1, 128>>>();

    dim3 gb((V_ + BV - 1) / BV, NTOK / BT);   // 79 x 64
    k_base<<<gb, 256>>>(src, X, W, edge, rel);

    k_stats<<<NTOK, 256>>>();

    k_final<<<dim3(NTOK / BMF, 2), 256>>>(W); // 64 x 2 = 128 CTAs, one wave

    k_combine<<<256, 256>>>(out);
    (void)X; (void)in_sizes; (void)n_in; (void)out_size;
}

// round 3
// speedup vs baseline: 2.1772x; 1.3161x over previous
#include <cuda_runtime.h>

#define V_     10000
#define VPAD   10240
#define E_     128
#define NTOK   2048
#define NR     8

// ---------------- scratch (device globals; no allocations) ----------------
__device__ float         g_base[(size_t)NTOK * VPAD];   // base scores, padded rows (pad = 0)
__device__ unsigned char g_cls [(size_t)NTOK * VPAD];   // relation class 0..8; pad stays 0 (zero-init)
__device__ float         g_colsum[E_];                  // column sums of W
__device__ float         g_part[40 * E_];               // colsum partials
__device__ float         g_stats[NTOK * 12];            // per token: K1[8], beta, (pad)
__device__ float         g_psum[4][(size_t)NTOK * E_];  // K-split partial outputs

__device__ __forceinline__ void fma2(unsigned long long& acc,
                                     unsigned long long a, unsigned long long b) {
    asm("fma.rn.f32x2 %0, %1, %2, %0;" : "+l"(acc) : "l"(a), "l"(b));
}

// ---------------- column sums of W (deterministic 2-stage) ----------------
__global__ void k_colsum1(const float* __restrict__ W) {
    int b = blockIdx.x, col = threadIdx.x;
    float s = 0.f;
    int v0 = b * 250;
    for (int v = v0; v < v0 + 250; v++) s += W[v * E_ + col];
    g_part[b * E_ + col] = s;
}
__global__ void k_colsum2() {
    int col = threadIdx.x;
    float s = 0.f;
    for (int b = 0; b < 40; b++) s += g_part[b * E_ + col];
    g_colsum[col] = s;
}

// ---------------- base GEMM (f32x2) + classification ----------------
#define BT 32
#define BV 128
#define KCB 32

__global__ __launch_bounds__(256) void k_base(
    const int*   __restrict__ src,
    const float* __restrict__ X,      // src_embed [NTOK, E]
    const float* __restrict__ W,      // embed_weight [V, E]
    const float* __restrict__ edge,   // [V, V]
    const int*   __restrict__ rel)    // [V, V]
{
    __shared__ float Xs2[KCB][72];        // duplicated (x,x) pairs, 2*BT=64 used, stride 72
    __shared__ float Ws[KCB][BV + 4];
    __shared__ int   ssm[BT];

    int tid  = threadIdx.x;
    int vblk = blockIdx.x * BV;
    int tblk = blockIdx.y * BT;

    if (tid < BT) ssm[tid] = src[tblk + tid];

    unsigned long long acc[4][2];
#pragma unroll
    for (int i = 0; i < 4; i++) { acc[i][0] = 0ull; acc[i][1] = 0ull; }

    int tx = tid & 31;   // v quad
    int ty = tid >> 5;   // token quad

    for (int kc = 0; kc < E_; kc += KCB) {
        __syncthreads();
        // X chunk 32 tokens x 32 k, duplicated pairs, coalesced gmem
#pragma unroll
        for (int j = 0; j < 4; j++) {
            int idx = tid + 256 * j;
            int t = idx >> 5, k = idx & 31;
            float x = X[(tblk + t) * E_ + kc + k];
            *(float2*)&Xs2[k][2 * t] = make_float2(x, x);
        }
        // W chunk 128 v x 32 k, k-major transpose
#pragma unroll
        for (int j = 0; j < 16; j++) {
            int idx = tid + 256 * j;
            int v = idx >> 5, k = idx & 31;
            int gv = vblk + v;
            Ws[k][v] = (gv < V_) ? W[gv * E_ + kc + k] : 0.f;
        }
        __syncthreads();
#pragma unroll
        for (int kk = 0; kk < KCB; kk++) {
            ulonglong2 w2  = *(const ulonglong2*)&Ws[kk][4 * tx];
            ulonglong2 a01 = *(const ulonglong2*)&Xs2[kk][8 * ty];
            ulonglong2 a23 = *(const ulonglong2*)&Xs2[kk][8 * ty + 4];
            fma2(acc[0][0], a01.x, w2.x); fma2(acc[0][1], a01.x, w2.y);
            fma2(acc[1][0], a01.y, w2.x); fma2(acc[1][1], a01.y, w2.y);
            fma2(acc[2][0], a23.x, w2.x); fma2(acc[2][1], a23.x, w2.y);
            fma2(acc[3][0], a23.y, w2.x); fma2(acc[3][1], a23.y, w2.y);
        }
    }

    int v0 = vblk + 4 * tx;
#pragma unroll
    for (int i = 0; i < 4; i++) {
        int tl = 4 * ty + i;
        int t  = tblk + tl;
        float2 lo = *(float2*)&acc[i][0];
        float2 hi = *(float2*)&acc[i][1];
        float4 bb = make_float4(lo.x, lo.y, hi.x, hi.y);
        *(float4*)&g_base[(size_t)t * VPAD + v0] = bb;
        if (v0 < V_) {
            long s = ssm[tl];
            int4   r4 = *(const int4*)  (rel  + s * (long)V_ + v0);
            float4 e4 = *(const float4*)(edge + s * (long)V_ + v0);
            uchar4 c;
            c.x = (r4.x >= 1 && r4.x <= 8 && e4.x > 0.f) ? (unsigned char)r4.x : 0;
            c.y = (r4.y >= 1 && r4.y <= 8 && e4.y > 0.f) ? (unsigned char)r4.y : 0;
            c.z = (r4.z >= 1 && r4.z <= 8 && e4.z > 0.f) ? (unsigned char)r4.z : 0;
            c.w = (r4.w >= 1 && r4.w <= 8 && e4.w > 0.f) ? (unsigned char)r4.w : 0;
            *(uchar4*)&g_cls[(size_t)t * VPAD + v0] = c;
        }
    }
}

// ---------------- per-(t,r) softmax stats + mixture weights (M = 0) ----------------
__global__ __launch_bounds__(256) void k_stats() {
    int t   = blockIdx.x;
    int tid = threadIdx.x;
    __shared__ float red[8][36];
    __shared__ float fin[36];

    float e[NR], d[NR], b[NR], n[NR];
#pragma unroll
    for (int r = 0; r < NR; r++) { e[r] = 0.f; d[r] = 0.f; b[r] = 0.f; n[r] = 0.f; }
    float B = 0.f;

    const float*         baseRow = g_base + (size_t)t * VPAD;
    const unsigned char* clsRow  = g_cls  + (size_t)t * VPAD;

    for (int i = tid; i < V_ / 4; i += 256) {
        float4 b4 = *(const float4*)(baseRow + 4 * i);
        uchar4 c4 = *(const uchar4*)(clsRow + 4 * i);
        float bs[4] = {b4.x, b4.y, b4.z, b4.w};
        int   cc[4] = {c4.x, c4.y, c4.z, c4.w};
#pragma unroll
        for (int j = 0; j < 4; j++) {
            float v = bs[j];
            int   c = cc[j];
            B += v;
            float p  = __expf(v);
            float pv = p * v;
#pragma unroll
            for (int r = 0; r < NR; r++) {
                bool m = (c == r + 1);
                if (m) { e[r] += p; d[r] += pv; b[r] += v; n[r] += 1.f; }
            }
        }
    }

#pragma unroll
    for (int o = 16; o; o >>= 1) {
        B += __shfl_xor_sync(0xFFFFFFFFu, B, o);
#pragma unroll
        for (int r = 0; r < NR; r++) {
            e[r] += __shfl_xor_sync(0xFFFFFFFFu, e[r], o);
            d[r] += __shfl_xor_sync(0xFFFFFFFFu, d[r], o);
            b[r] += __shfl_xor_sync(0xFFFFFFFFu, b[r], o);
            n[r] += __shfl_xor_sync(0xFFFFFFFFu, n[r], o);
        }
    }
    int w = tid >> 5, lane = tid & 31;
    if (lane == 0) {
#pragma unroll
        for (int r = 0; r < NR; r++) {
            red[w][r]      = e[r];
            red[w][8 + r]  = d[r];
            red[w][16 + r] = b[r];
            red[w][24 + r] = n[r];
        }
        red[w][32] = B;
    }
    __syncthreads();
    if (tid < 33) {
        float s = 0.f;
#pragma unroll
        for (int k = 0; k < 8; k++) s += red[k][tid];
        fin[tid] = s;
    }
    __syncthreads();
    if (tid == 0) {
        float sc[NR], Zv[NR];
        float Bt = fin[32];
#pragma unroll
        for (int r = 0; r < NR; r++) {
            float Z = ((float)V_ - fin[24 + r]) + fin[r];   // bg = 1
            Zv[r] = Z;
            sc[r] = (fin[8 + r] + (Bt - fin[16 + r])) / Z;
        }
        float mx = sc[0];
#pragma unroll
        for (int r = 1; r < NR; r++) mx = fmaxf(mx, sc[r]);
        float es[NR], ss = 0.f;
#pragma unroll
        for (int r = 0; r < NR; r++) { es[r] = __expf(sc[r] - mx); ss += es[r]; }
        float inv = 1.f / ss;
        float beta = 0.f;
        float* st = g_stats + t * 12;
#pragma unroll
        for (int r = 0; r < NR; r++) {
            float K1 = es[r] * inv / Zv[r];
            st[r] = K1;
            beta += K1;           // K2 == K1 since bg = 1
        }
        st[8] = beta;
    }
}

// ---------------- final dense GEMM with on-the-fly gamma (double-buffered) ----------------
#define KCF    16
#define BMF    32
#define KSPLIT 4
#define KQ     (VPAD / KSPLIT)    // 2560
#define NCH    (KQ / KCF)         // 160

__global__ __launch_bounds__(256) void k_final(const float* __restrict__ W) {
    __shared__ float Ws[2][KCF][E_];      // 16 KB
    __shared__ float As2[2][KCF][72];     // 9 KB, gamma duplicated pairs, stride 72
    __shared__ float K1s[BMF][NR];

    int tid  = threadIdx.x;
    int t0   = blockIdx.x * BMF;
    int ks   = blockIdx.y;
    int k0   = ks * KQ;

    {   // per-token K1: 32 tokens x 8 relations == 256 threads
        int tok = tid >> 3, r = tid & 7;
        K1s[tok][r] = g_stats[(t0 + tok) * 12 + r];
    }
    __syncthreads();

    unsigned long long acc[4][2];
#pragma unroll
    for (int i = 0; i < 4; i++) { acc[i][0] = 0ull; acc[i][1] = 0ull; }

    int tx = tid & 31, ty = tid >> 5;

    // staging registers
    float4        wst[2];
    float2        bst;
    unsigned char cst0, cst1;
    int a_tok = tid >> 4;            // 0..15? no: 512 elems = 2/thread handled below
    // A element mapping: idx = tid + 256*jj -> tok = idx>>4? use per-thread: tok = tid>>3, v2 = (tid&7)*2
    int tokA = tid >> 3;             // 0..31
    int v2A  = (tid & 7) * 2;        // 0,2,..,14
    (void)a_tok;

    auto stage = [&](int kc) {
#pragma unroll
        for (int j = 0; j < 2; j++) {
            int p  = tid + 256 * j;
            int v  = p >> 5;
            int e4 = (p & 31) * 4;
            int gv = kc + v;
            wst[j] = (gv < V_) ? *(const float4*)&W[(size_t)gv * E_ + e4]
                               : make_float4(0.f, 0.f, 0.f, 0.f);
        }
        size_t off = (size_t)(t0 + tokA) * VPAD + kc + v2A;
        bst  = *(const float2*)(g_base + off);
        const unsigned char* cp = g_cls + off;
        cst0 = cp[0]; cst1 = cp[1];
    };
    auto commit = [&](int buf) {
#pragma unroll
        for (int j = 0; j < 2; j++) {
            int p  = tid + 256 * j;
            int v  = p >> 5;
            int e4 = (p & 31) * 4;
            *(float4*)&Ws[buf][v][e4] = wst[j];
        }
        float g0 = 0.f, g1 = 0.f;
        if (cst0) g0 = K1s[tokA][cst0 - 1] * (__expf(bst.x) - 1.f);
        if (cst1) g1 = K1s[tokA][cst1 - 1] * (__expf(bst.y) - 1.f);
        *(float2*)&As2[buf][v2A][2 * tokA]     = make_float2(g0, g0);
        *(float2*)&As2[buf][v2A + 1][2 * tokA] = make_float2(g1, g1);
    };

    stage(k0);
    commit(0);
    int buf = 0;

    for (int i = 0; i < NCH; i++) {
        __syncthreads();
        if (i + 1 < NCH) stage(k0 + (i + 1) * KCF);
#pragma unroll
        for (int kk = 0; kk < KCF; kk++) {
            ulonglong2 w2  = *(const ulonglong2*)&Ws[buf][kk][4 * tx];
            ulonglong2 a01 = *(const ulonglong2*)&As2[buf][kk][8 * ty];
            ulonglong2 a23 = *(const ulonglong2*)&As2[buf][kk][8 * ty + 4];
            fma2(acc[0][0], a01.x, w2.x); fma2(acc[0][1], a01.x, w2.y);
            fma2(acc[1][0], a01.y, w2.x); fma2(acc[1][1], a01.y, w2.y);
            fma2(acc[2][0], a23.x, w2.x); fma2(acc[2][1], a23.x, w2.y);
            fma2(acc[3][0], a23.y, w2.x); fma2(acc[3][1], a23.y, w2.y);
        }
        if (i + 1 < NCH) commit(buf ^ 1);
        buf ^= 1;
    }

    float* ps = g_psum[ks];
#pragma unroll
    for (int i = 0; i < 4; i++) {
        int t = t0 + 4 * ty + i;
        float2 lo = *(float2*)&acc[i][0];
        float2 hi = *(float2*)&acc[i][1];
        *(float4*)&ps[(size_t)t * E_ + 4 * tx] = make_float4(lo.x, lo.y, hi.x, hi.y);
    }
}

// ---------------- combine K-split partials + background term ----------------
__global__ void k_combine(float* __restrict__ out) {
    int i  = blockIdx.x * 256 + threadIdx.x;  // float4 index; 65536 total
    int t  = i >> 5;
    int c4 = (i & 31) * 4;
    size_t off = (size_t)t * E_ + c4;
    float4 a0 = *(const float4*)&g_psum[0][off];
    float4 a1 = *(const float4*)&g_psum[1][off];
    float4 a2 = *(const float4*)&g_psum[2][off];
    float4 a3 = *(const float4*)&g_psum[3][off];
    float  beta = g_stats[t * 12 + 8];
    float4 cs = *(const float4*)&g_colsum[c4];
    float4 o;
    o.x = a0.x + a1.x + a2.x + a3.x + beta * cs.x;
    o.y = a0.y + a1.y + a2.y + a3.y + beta * cs.y;
    o.z = a0.z + a1.z + a2.z + a3.z + beta * cs.z;
    o.w = a0.w + a1.w + a2.w + a3.w + beta * cs.w;
    *(float4*)&out[off] = o;
}

// ---------------- launch ----------------
extern "C" void kernel_launch(void* const* d_in, const int* in_sizes, int n_in,
                              void* d_out, int out_size) {
    const int*   src  = (const int*)  d_in[0];
    const float* X    = (const float*)d_in[1];
    const float* W    = (const float*)d_in[2];
    const float* edge = (const float*)d_in[3];
    const int*   rel  = (const int*)  d_in[4];
    float* out = (float*)d_out;

    k_colsum1<<<40, 128>>>(W);
    k_colsum2<<<1, 128>>>();

    dim3 gb((V_ + BV - 1) / BV, NTOK / BT);   // 79 x 64
    k_base<<<gb, 256>>>(src, X, W, edge, rel);

    k_stats<<<NTOK, 256>>>();

    k_final<<<dim3(NTOK / BMF, KSPLIT), 256>>>(W);  // 64 x 4 = 256 CTAs

    k_combine<<<256, 256>>>(out);
    (void)in_sizes; (void)n_in; (void)out_size;
}

// round 4
// speedup vs baseline: 2.9016x; 1.3327x over previous
#include <cuda_runtime.h>

#define V_     10000
#define VPAD   10240
#define E_     128
#define NTOK   2048
#define NR     8

#define KSPLIT 9
#define KQ     1152          // 9*1152 = 10368 covers VPAD with guards

// ---------------- scratch (device globals; no allocations) ----------------
__device__ float         g_base[(size_t)NTOK * VPAD];   // base scores (pad cols = 0)
__device__ unsigned char g_cls [(size_t)NTOK * VPAD];   // class 0..8; pad stays 0
__device__ float         g_colsum[E_];
__device__ float         g_part[40 * E_];
__device__ float         g_stats[NTOK * 12];             // K1[8], beta
__device__ float         g_psum[KSPLIT][(size_t)NTOK * E_];

__device__ __forceinline__ void fma2(unsigned long long& acc,
                                     unsigned long long a, unsigned long long b) {
    asm("fma.rn.f32x2 %0, %1, %2, %0;" : "+l"(acc) : "l"(a), "l"(b));
}

// ---------------- column sums of W (deterministic 2-stage) ----------------
__global__ void k_colsum1(const float* __restrict__ W) {
    int b = blockIdx.x, col = threadIdx.x;
    float s = 0.f;
    int v0 = b * 250;
    for (int v = v0; v < v0 + 250; v++) s += W[v * E_ + col];
    g_part[b * E_ + col] = s;
}
__global__ void k_colsum2() {
    int col = threadIdx.x;
    float s = 0.f;
    for (int b = 0; b < 40; b++) s += g_part[b * E_ + col];
    g_colsum[col] = s;
}

// ---------------- base GEMM (f32x2, 8x8 thread tile) + classification ----------------
#define BT 64
#define BV 128
#define KCB 32
#define XST 132
#define WST 132

__global__ __launch_bounds__(128) void k_base(
    const int*   __restrict__ src,
    const float* __restrict__ X,
    const float* __restrict__ W,
    const float* __restrict__ edge,
    const int*   __restrict__ rel)
{
    __shared__ float Xs2[KCB][XST];   // 64 tokens duplicated as (x,x) pairs
    __shared__ float Ws[KCB][WST];    // 128 v, k-major
    __shared__ int   ssm[BT];

    int tid  = threadIdx.x;
    int vblk = blockIdx.x * BV;
    int tblk = blockIdx.y * BT;
    if (tid < BT) ssm[tid] = src[tblk + tid];

    unsigned long long acc[8][4];
#pragma unroll
    for (int i = 0; i < 8; i++)
#pragma unroll
        for (int j = 0; j < 4; j++) acc[i][j] = 0ull;

    int tx = tid & 15;     // col group: cols 8*tx..8*tx+7
    int ty = tid >> 4;     // token group: tokens 8*ty..8*ty+7
    int xtok = tid & 63, xkq = tid >> 6;   // X load map
    int gvW  = vblk + tid;                 // W load map (one v-row per thread)

    for (int kc = 0; kc < E_; kc += KCB) {
        __syncthreads();
        // X tile: 64 tok x 32 k, duplicated pairs
#pragma unroll
        for (int j = 0; j < 4; j++) {
            int k4 = 4 * (xkq + 2 * j);
            float4 x4 = *(const float4*)&X[(size_t)(tblk + xtok) * E_ + kc + k4];
            *(float2*)&Xs2[k4 + 0][2 * xtok] = make_float2(x4.x, x4.x);
            *(float2*)&Xs2[k4 + 1][2 * xtok] = make_float2(x4.y, x4.y);
            *(float2*)&Xs2[k4 + 2][2 * xtok] = make_float2(x4.z, x4.z);
            *(float2*)&Xs2[k4 + 3][2 * xtok] = make_float2(x4.w, x4.w);
        }
        // W tile: 128 v x 32 k, transposed, conflict-free stores
#pragma unroll
        for (int j = 0; j < 8; j++) {
            int k4 = 4 * j;
            float4 w4 = (gvW < V_) ? *(const float4*)&W[(size_t)gvW * E_ + kc + k4]
                                   : make_float4(0.f, 0.f, 0.f, 0.f);
            Ws[k4 + 0][tid] = w4.x;
            Ws[k4 + 1][tid] = w4.y;
            Ws[k4 + 2][tid] = w4.z;
            Ws[k4 + 3][tid] = w4.w;
        }
        __syncthreads();
#pragma unroll
        for (int kk = 0; kk < KCB; kk++) {
            ulonglong2 w01 = *(const ulonglong2*)&Ws[kk][8 * tx];
            ulonglong2 w23 = *(const ulonglong2*)&Ws[kk][8 * tx + 4];
            ulonglong2 a01 = *(const ulonglong2*)&Xs2[kk][16 * ty];
            ulonglong2 a23 = *(const ulonglong2*)&Xs2[kk][16 * ty + 4];
            ulonglong2 a45 = *(const ulonglong2*)&Xs2[kk][16 * ty + 8];
            ulonglong2 a67 = *(const ulonglong2*)&Xs2[kk][16 * ty + 12];
            unsigned long long a[8] = {a01.x, a01.y, a23.x, a23.y,
                                       a45.x, a45.y, a67.x, a67.y};
            unsigned long long w[4] = {w01.x, w01.y, w23.x, w23.y};
#pragma unroll
            for (int i = 0; i < 8; i++)
#pragma unroll
                for (int j = 0; j < 4; j++)
                    fma2(acc[i][j], a[i], w[j]);
        }
    }

    int v0 = vblk + 8 * tx;
#pragma unroll
    for (int i = 0; i < 8; i++) {
        int tl = 8 * ty + i;
        int t  = tblk + tl;
        float2 p0 = *(float2*)&acc[i][0];
        float2 p1 = *(float2*)&acc[i][1];
        float2 p2 = *(float2*)&acc[i][2];
        float2 p3 = *(float2*)&acc[i][3];
        *(float4*)&g_base[(size_t)t * VPAD + v0]     = make_float4(p0.x, p0.y, p1.x, p1.y);
        *(float4*)&g_base[(size_t)t * VPAD + v0 + 4] = make_float4(p2.x, p2.y, p3.x, p3.y);
        if (v0 < V_) {
            long s = ssm[tl];
#pragma unroll
            for (int h = 0; h < 2; h++) {
                int vv = v0 + 4 * h;
                int4   r4 = *(const int4*)  (rel  + s * (long)V_ + vv);
                float4 e4 = *(const float4*)(edge + s * (long)V_ + vv);
                uchar4 c;
                c.x = (r4.x >= 1 && r4.x <= 8 && e4.x > 0.f) ? (unsigned char)r4.x : 0;
                c.y = (r4.y >= 1 && r4.y <= 8 && e4.y > 0.f) ? (unsigned char)r4.y : 0;
                c.z = (r4.z >= 1 && r4.z <= 8 && e4.z > 0.f) ? (unsigned char)r4.z : 0;
                c.w = (r4.w >= 1 && r4.w <= 8 && e4.w > 0.f) ? (unsigned char)r4.w : 0;
                *(uchar4*)&g_cls[(size_t)t * VPAD + vv] = c;
            }
        }
    }
}

// ---------------- per-(t,r) stats: Z_r = V + sum q, num_r = B + sum q*v ----------------
__global__ __launch_bounds__(256) void k_stats() {
    int t   = blockIdx.x;
    int tid = threadIdx.x;
    __shared__ float red[8][20];
    __shared__ float fin[20];

    float e[NR], d[NR];
#pragma unroll
    for (int r = 0; r < NR; r++) { e[r] = 0.f; d[r] = 0.f; }
    float B = 0.f;

    const float*         baseRow = g_base + (size_t)t * VPAD;
    const unsigned char* clsRow  = g_cls  + (size_t)t * VPAD;

    for (int i = tid; i < V_ / 4; i += 256) {
        float4 b4 = *(const float4*)(baseRow + 4 * i);
        uchar4 c4 = *(const uchar4*)(clsRow + 4 * i);
        float bs[4] = {b4.x, b4.y, b4.z, b4.w};
        int   cc[4] = {c4.x, c4.y, c4.z, c4.w};
#pragma unroll
        for (int j = 0; j < 4; j++) {
            float v = bs[j];
            int   c = cc[j];
            B += v;
            float q  = __expf(v) - 1.f;
            float qv = q * v;
#pragma unroll
            for (int r = 0; r < NR; r++) {
                if (c == r + 1) { e[r] += q; d[r] += qv; }
            }
        }
    }

#pragma unroll
    for (int o = 16; o; o >>= 1) {
        B += __shfl_xor_sync(0xFFFFFFFFu, B, o);
#pragma unroll
        for (int r = 0; r < NR; r++) {
            e[r] += __shfl_xor_sync(0xFFFFFFFFu, e[r], o);
            d[r] += __shfl_xor_sync(0xFFFFFFFFu, d[r], o);
        }
    }
    int w = tid >> 5, lane = tid & 31;
    if (lane == 0) {
#pragma unroll
        for (int r = 0; r < NR; r++) {
            red[w][r]     = e[r];
            red[w][8 + r] = d[r];
        }
        red[w][16] = B;
    }
    __syncthreads();
    if (tid < 17) {
        float s = 0.f;
#pragma unroll
        for (int k = 0; k < 8; k++) s += red[k][tid];
        fin[tid] = s;
    }
    __syncthreads();
    if (tid == 0) {
        float sc[NR], Zv[NR];
        float Bt = fin[16];
#pragma unroll
        for (int r = 0; r < NR; r++) {
            float Z = (float)V_ + fin[r];
            Zv[r] = Z;
            sc[r] = (fin[8 + r] + Bt) / Z;
        }
        float mx = sc[0];
#pragma unroll
        for (int r = 1; r < NR; r++) mx = fmaxf(mx, sc[r]);
        float es[NR], ss = 0.f;
#pragma unroll
        for (int r = 0; r < NR; r++) { es[r] = __expf(sc[r] - mx); ss += es[r]; }
        float inv = 1.f / ss;
        float beta = 0.f;
        float* st = g_stats + t * 12;
#pragma unroll
        for (int r = 0; r < NR; r++) {
            float K1 = es[r] * inv / Zv[r];
            st[r] = K1;
            beta += K1;
        }
        st[8] = beta;
    }
}

// ---------------- final GEMM, on-the-fly gamma, 8x8 tile, double-buffered ----------------
#define BMF  64
#define KCF  16
#define NCHF (KQ / KCF)      // 72

__global__ __launch_bounds__(128) void k_final(const float* __restrict__ W) {
    __shared__ float Ws[2][KCF][E_];      // 16 KB
    __shared__ float As2[2][KCF][132];    // 16.9 KB
    __shared__ float K1s[BMF][NR];

    int tid = threadIdx.x;
    int t0  = blockIdx.x * BMF;
    int ks  = blockIdx.y;
    int k0  = ks * KQ;

#pragma unroll
    for (int j = 0; j < 4; j++) {
        int idx = tid + 128 * j;
        K1s[idx >> 3][idx & 7] = g_stats[(t0 + (idx >> 3)) * 12 + (idx & 7)];
    }
    __syncthreads();

    unsigned long long acc[8][4];
#pragma unroll
    for (int i = 0; i < 8; i++)
#pragma unroll
        for (int j = 0; j < 4; j++) acc[i][j] = 0ull;

    int tx = tid & 15, ty = tid >> 4;
    int tokA = tid >> 1, kA = (tid & 1) * 8;

    float4 wst[4];
    float4 bst[2];
    uchar4 cst[2];

    auto stage = [&](int kc) {
#pragma unroll
        for (int j = 0; j < 4; j++) {
            int p  = tid + 128 * j;
            int v  = p >> 5;
            int e4 = (p & 31) * 4;
            int gv = kc + v;
            wst[j] = (gv < V_) ? *(const float4*)&W[(size_t)gv * E_ + e4]
                               : make_float4(0.f, 0.f, 0.f, 0.f);
        }
        int gb = kc + kA;
        if (gb < V_) {
            size_t off = (size_t)(t0 + tokA) * VPAD + gb;
            bst[0] = *(const float4*)(g_base + off);
            bst[1] = *(const float4*)(g_base + off + 4);
            cst[0] = *(const uchar4*)(g_cls + off);
            cst[1] = *(const uchar4*)(g_cls + off + 4);
        } else {
            bst[0] = bst[1] = make_float4(0.f, 0.f, 0.f, 0.f);
            cst[0] = cst[1] = make_uchar4(0, 0, 0, 0);
        }
    };
    auto commit = [&](int buf) {
#pragma unroll
        for (int j = 0; j < 4; j++) {
            int p  = tid + 128 * j;
            int v  = p >> 5;
            int e4 = (p & 31) * 4;
            *(float4*)&Ws[buf][v][e4] = wst[j];
        }
#pragma unroll
        for (int h = 0; h < 2; h++) {
            float bb[4] = {bst[h].x, bst[h].y, bst[h].z, bst[h].w};
            unsigned char ccs[4] = {cst[h].x, cst[h].y, cst[h].z, cst[h].w};
#pragma unroll
            for (int j = 0; j < 4; j++) {
                float g = 0.f;
                int c = ccs[j];
                if (c) g = K1s[tokA][c - 1] * (__expf(bb[j]) - 1.f);
                *(float2*)&As2[buf][kA + 4 * h + j][2 * tokA] = make_float2(g, g);
            }
        }
    };

    stage(k0);
    commit(0);
    int buf = 0;

    for (int i = 0; i < NCHF; i++) {
        __syncthreads();
        if (i + 1 < NCHF) stage(k0 + (i + 1) * KCF);
#pragma unroll
        for (int kk = 0; kk < KCF; kk++) {
            ulonglong2 w01 = *(const ulonglong2*)&Ws[buf][kk][8 * tx];
            ulonglong2 w23 = *(const ulonglong2*)&Ws[buf][kk][8 * tx + 4];
            ulonglong2 a01 = *(const ulonglong2*)&As2[buf][kk][16 * ty];
            ulonglong2 a23 = *(const ulonglong2*)&As2[buf][kk][16 * ty + 4];
            ulonglong2 a45 = *(const ulonglong2*)&As2[buf][kk][16 * ty + 8];
            ulonglong2 a67 = *(const ulonglong2*)&As2[buf][kk][16 * ty + 12];
            unsigned long long a[8] = {a01.x, a01.y, a23.x, a23.y,
                                       a45.x, a45.y, a67.x, a67.y};
            unsigned long long w[4] = {w01.x, w01.y, w23.x, w23.y};
#pragma unroll
            for (int ii = 0; ii < 8; ii++)
#pragma unroll
                for (int jj = 0; jj < 4; jj++)
                    fma2(acc[ii][jj], a[ii], w[jj]);
        }
        if (i + 1 < NCHF) commit(buf ^ 1);
        buf ^= 1;
    }

    float* ps = g_psum[ks];
#pragma unroll
    for (int i = 0; i < 8; i++) {
        int t = t0 + 8 * ty + i;
        float2 p0 = *(float2*)&acc[i][0];
        float2 p1 = *(float2*)&acc[i][1];
        float2 p2 = *(float2*)&acc[i][2];
        float2 p3 = *(float2*)&acc[i][3];
        *(float4*)&ps[(size_t)t * E_ + 8 * tx]     = make_float4(p0.x, p0.y, p1.x, p1.y);
        *(float4*)&ps[(size_t)t * E_ + 8 * tx + 4] = make_float4(p2.x, p2.y, p3.x, p3.y);
    }
}

// ---------------- combine K-split partials + background term ----------------
__global__ void k_combine(float* __restrict__ out) {
    int i  = blockIdx.x * 256 + threadIdx.x;   // 65536 float4
    int t  = i >> 5;
    int c4 = (i & 31) * 4;
    size_t off = (size_t)t * E_ + c4;
    float  beta = g_stats[t * 12 + 8];
    float4 cs = *(const float4*)&g_colsum[c4];
    float4 o = make_float4(beta * cs.x, beta * cs.y, beta * cs.z, beta * cs.w);
#pragma unroll
    for (int r = 0; r < KSPLIT; r++) {
        float4 a = *(const float4*)&g_psum[r][off];
        o.x += a.x; o.y += a.y; o.z += a.z; o.w += a.w;
    }
    *(float4*)&out[off] = o;
}

// ---------------- launch ----------------
extern "C" void kernel_launch(void* const* d_in, const int* in_sizes, int n_in,
                              void* d_out, int out_size) {
    const int*   src  = (const int*)  d_in[0];
    const float* X    = (const float*)d_in[1];
    const float* W    = (const float*)d_in[2];
    const float* edge = (const float*)d_in[3];
    const int*   rel  = (const int*)  d_in[4];
    float* out = (float*)d_out;

    k_colsum1<<<40, 128>>>(W);
    k_colsum2<<<1, 128>>>();

    dim3 gb((V_ + BV - 1) / BV, NTOK / BT);   // 79 x 32
    k_base<<<gb, 128>>>(src, X, W, edge, rel);

    k_stats<<<NTOK, 256>>>();

    k_final<<<dim3(NTOK / BMF, KSPLIT), 128>>>(W);  // 32 x 9 = 288 CTAs

    k_combine<<<256, 256>>>(out);
    (void)in_sizes; (void)n_in; (void)out_size;
}

// round 5
// speedup vs baseline: 2.9253x; 1.0082x over previous
#include <cuda_runtime.h>
#include <cstdint>

#define V_     10000
#define VPAD   10240
#define E_     128
#define NTOK   2048
#define NR     8

#define KSPLIT 9
#define KQ     1152          // 9*1152 = 10368 covers VPAD with guards

// ---------------- scratch (device globals; no allocations) ----------------
__device__ float         g_base[(size_t)NTOK * VPAD];   // base scores (pad cols = 0)
__device__ unsigned char g_cls [(size_t)NTOK * VPAD];   // class 0..8; pad stays 0
__device__ float         g_colsum[E_];
__device__ float         g_part[40 * E_];
__device__ float         g_stats[NTOK * 12];             // K1[8], beta
__device__ float         g_psum[KSPLIT][(size_t)NTOK * E_];

__device__ __forceinline__ void fma2(unsigned long long& acc,
                                     unsigned long long a, unsigned long long b) {
    asm("fma.rn.f32x2 %0, %1, %2, %0;" : "+l"(acc) : "l"(a), "l"(b));
}
__device__ __forceinline__ uint32_t s2u(const void* p) {
    return (uint32_t)__cvta_generic_to_shared(p);
}
#define CP_ASYNC16(dst, src) \
    asm volatile("cp.async.cg.shared.global [%0], [%1], 16;\n" :: "r"(dst), "l"(src))
#define CP_COMMIT() asm volatile("cp.async.commit_group;\n" ::: "memory")
#define CP_WAIT0()  asm volatile("cp.async.wait_group 0;\n" ::: "memory")

// ---------------- column sums of W (deterministic 2-stage) ----------------
__global__ void k_colsum1(const float* __restrict__ W) {
    int b = blockIdx.x, col = threadIdx.x;
    float s = 0.f;
    int v0 = b * 250;
    for (int v = v0; v < v0 + 250; v++) s += W[v * E_ + col];
    g_part[b * E_ + col] = s;
}
__global__ void k_colsum2() {
    int col = threadIdx.x;
    float s = 0.f;
    for (int b = 0; b < 40; b++) s += g_part[b * E_ + col];
    g_colsum[col] = s;
}

// ---------------- base GEMM (f32x2, 8x8 tile) + cp.async-prefetched classify ----------------
#define BT 64
#define BV 128
#define KCB 32

// dynamic smem layout (bytes)
#define OFF_XS2  0
#define OFF_WS   16896
#define OFF_REL  33792
#define OFF_EDGE 66560
#define OFF_SSM  99328
#define SMEM_KB  (99328 + 256)

__global__ __launch_bounds__(128) void k_base(
    const int*   __restrict__ src,
    const float* __restrict__ X,
    const float* __restrict__ W,
    const float* __restrict__ edge,
    const int*   __restrict__ rel)
{
    extern __shared__ char smraw[];
    float (*Xs2)[132] = (float(*)[132])(smraw + OFF_XS2);
    float (*Ws)[132]  = (float(*)[132])(smraw + OFF_WS);
    int*    rel_s  = (int*)  (smraw + OFF_REL);    // [64 tok][128 v]
    float*  edge_s = (float*)(smraw + OFF_EDGE);   // [64 tok][128 v]
    int*    ssm    = (int*)  (smraw + OFF_SSM);

    int tid  = threadIdx.x;
    int vblk = blockIdx.x * BV;
    int tblk = blockIdx.y * BT;
    if (tid < BT) ssm[tid] = src[tblk + tid];
    __syncthreads();

    // prefetch rel/edge tiles (64 tok x 128 v) via cp.async — hidden under GEMM
    uint32_t rel_su  = s2u(rel_s);
    uint32_t edge_su = s2u(edge_s);
#pragma unroll
    for (int j = 0; j < 16; j++) {
        int chunk = tid + 128 * j;          // 0..2047, 16B chunks
        int tok = chunk >> 5;
        int vloc = (chunk & 31) * 4;
        int v = vblk + vloc;
        if (v < V_) {
            long s = ssm[tok];
            CP_ASYNC16(rel_su  + chunk * 16, rel  + s * (long)V_ + v);
            CP_ASYNC16(edge_su + chunk * 16, edge + s * (long)V_ + v);
        }
    }
    CP_COMMIT();

    unsigned long long acc[8][4];
#pragma unroll
    for (int i = 0; i < 8; i++)
#pragma unroll
        for (int j = 0; j < 4; j++) acc[i][j] = 0ull;

    int tx = tid & 15;     // col group: 8*tx..8*tx+7
    int ty = tid >> 4;     // token group: 8*ty..8*ty+7
    int xtok = tid & 63, xkq = tid >> 6;
    int gvW  = vblk + tid;

    for (int kc = 0; kc < E_; kc += KCB) {
        __syncthreads();
#pragma unroll
        for (int j = 0; j < 4; j++) {
            int k4 = 4 * (xkq + 2 * j);
            float4 x4 = *(const float4*)&X[(size_t)(tblk + xtok) * E_ + kc + k4];
            *(float2*)&Xs2[k4 + 0][2 * xtok] = make_float2(x4.x, x4.x);
            *(float2*)&Xs2[k4 + 1][2 * xtok] = make_float2(x4.y, x4.y);
            *(float2*)&Xs2[k4 + 2][2 * xtok] = make_float2(x4.z, x4.z);
            *(float2*)&Xs2[k4 + 3][2 * xtok] = make_float2(x4.w, x4.w);
        }
#pragma unroll
        for (int j = 0; j < 8; j++) {
            int k4 = 4 * j;
            float4 w4 = (gvW < V_) ? *(const float4*)&W[(size_t)gvW * E_ + kc + k4]
                                   : make_float4(0.f, 0.f, 0.f, 0.f);
            Ws[k4 + 0][tid] = w4.x;
            Ws[k4 + 1][tid] = w4.y;
            Ws[k4 + 2][tid] = w4.z;
            Ws[k4 + 3][tid] = w4.w;
        }
        __syncthreads();
#pragma unroll
        for (int kk = 0; kk < KCB; kk++) {
            ulonglong2 w01 = *(const ulonglong2*)&Ws[kk][8 * tx];
            ulonglong2 w23 = *(const ulonglong2*)&Ws[kk][8 * tx + 4];
            ulonglong2 a01 = *(const ulonglong2*)&Xs2[kk][16 * ty];
            ulonglong2 a23 = *(const ulonglong2*)&Xs2[kk][16 * ty + 4];
            ulonglong2 a45 = *(const ulonglong2*)&Xs2[kk][16 * ty + 8];
            ulonglong2 a67 = *(const ulonglong2*)&Xs2[kk][16 * ty + 12];
            unsigned long long a[8] = {a01.x, a01.y, a23.x, a23.y,
                                       a45.x, a45.y, a67.x, a67.y};
            unsigned long long w[4] = {w01.x, w01.y, w23.x, w23.y};
#pragma unroll
            for (int i = 0; i < 8; i++)
#pragma unroll
                for (int j = 0; j < 4; j++)
                    fma2(acc[i][j], a[i], w[j]);
        }
    }

    CP_WAIT0();
    __syncthreads();

    int v0 = vblk + 8 * tx;
#pragma unroll
    for (int i = 0; i < 8; i++) {
        int tl = 8 * ty + i;
        int t  = tblk + tl;
        float2 p0 = *(float2*)&acc[i][0];
        float2 p1 = *(float2*)&acc[i][1];
        float2 p2 = *(float2*)&acc[i][2];
        float2 p3 = *(float2*)&acc[i][3];
        *(float4*)&g_base[(size_t)t * VPAD + v0]     = make_float4(p0.x, p0.y, p1.x, p1.y);
        *(float4*)&g_base[(size_t)t * VPAD + v0 + 4] = make_float4(p2.x, p2.y, p3.x, p3.y);
        if (v0 < V_) {
#pragma unroll
            for (int h = 0; h < 2; h++) {
                int vloc = 8 * tx + 4 * h;
                int4   r4 = *(const int4*)  &rel_s [tl * 128 + vloc];
                float4 e4 = *(const float4*)&edge_s[tl * 128 + vloc];
                uchar4 c;
                c.x = (r4.x >= 1 && r4.x <= 8 && e4.x > 0.f) ? (unsigned char)r4.x : 0;
                c.y = (r4.y >= 1 && r4.y <= 8 && e4.y > 0.f) ? (unsigned char)r4.y : 0;
                c.z = (r4.z >= 1 && r4.z <= 8 && e4.z > 0.f) ? (unsigned char)r4.z : 0;
                c.w = (r4.w >= 1 && r4.w <= 8 && e4.w > 0.f) ? (unsigned char)r4.w : 0;
                *(uchar4*)&g_cls[(size_t)t * VPAD + v0 + 4 * h] = c;
            }
        }
    }
}

// ---------------- per-(t,r) stats: lane-private smem RMW (deterministic) ----------------
#define CSTRIDE 33    // class slot stride in float2 units

__global__ __launch_bounds__(256) void k_stats() {
    __shared__ float2 accs[8][9 * CSTRIDE];   // [warp][class*33 + lane]
    __shared__ float  eArr[NR], dArr[NR], Bsh[8];

    int t   = blockIdx.x;
    int tid = threadIdx.x;
    int w   = tid >> 5, lane = tid & 31;

    for (int i = tid; i < 8 * 9 * CSTRIDE; i += 256)
        ((float2*)accs)[i] = make_float2(0.f, 0.f);
    __syncthreads();

    float B = 0.f;
    const float*         baseRow = g_base + (size_t)t * VPAD;
    const unsigned char* clsRow  = g_cls  + (size_t)t * VPAD;

    for (int i = tid; i < V_ / 4; i += 256) {
        float4 b4 = *(const float4*)(baseRow + 4 * i);
        uchar4 c4 = *(const uchar4*)(clsRow + 4 * i);
        float bs[4] = {b4.x, b4.y, b4.z, b4.w};
        int   cc[4] = {c4.x, c4.y, c4.z, c4.w};
#pragma unroll
        for (int j = 0; j < 4; j++) {
            float v = bs[j];
            B += v;
            float q = __expf(v) - 1.f;
            float2* p = &accs[w][cc[j] * CSTRIDE + lane];
            float2 o = *p;
            o.x += q;
            o.y = fmaf(q, v, o.y);
            *p = o;
        }
    }
    // B warp-reduce
#pragma unroll
    for (int o = 16; o; o >>= 1) B += __shfl_xor_sync(0xFFFFFFFFu, B, o);
    if (lane == 0) Bsh[w] = B;
    __syncthreads();

    // class reduce: warp w handles class w+1
    {
        float2 s = make_float2(0.f, 0.f);
#pragma unroll
        for (int ww = 0; ww < 8; ww++) {
            float2 a = accs[ww][(w + 1) * CSTRIDE + lane];
            s.x += a.x; s.y += a.y;
        }
#pragma unroll
        for (int o = 16; o; o >>= 1) {
            s.x += __shfl_xor_sync(0xFFFFFFFFu, s.x, o);
            s.y += __shfl_xor_sync(0xFFFFFFFFu, s.y, o);
        }
        if (lane == 0) { eArr[w] = s.x; dArr[w] = s.y; }
    }
    __syncthreads();

    if (tid == 0) {
        float Bt = 0.f;
#pragma unroll
        for (int k = 0; k < 8; k++) Bt += Bsh[k];
        float sc[NR], Zv[NR];
#pragma unroll
        for (int r = 0; r < NR; r++) {
            float Z = (float)V_ + eArr[r];
            Zv[r] = Z;
            sc[r] = (dArr[r] + Bt) / Z;
        }
        float mx = sc[0];
#pragma unroll
        for (int r = 1; r < NR; r++) mx = fmaxf(mx, sc[r]);
        float es[NR], ss = 0.f;
#pragma unroll
        for (int r = 0; r < NR; r++) { es[r] = __expf(sc[r] - mx); ss += es[r]; }
        float inv = 1.f / ss;
        float beta = 0.f;
        float* st = g_stats + t * 12;
#pragma unroll
        for (int r = 0; r < NR; r++) {
            float K1 = es[r] * inv / Zv[r];
            st[r] = K1;
            beta += K1;
        }
        st[8] = beta;
    }
}

// ---------------- final GEMM, on-the-fly gamma, 8x8 tile, double-buffered ----------------
#define BMF  64
#define KCF  16
#define NCHF (KQ / KCF)      // 72

__global__ __launch_bounds__(128) void k_final(const float* __restrict__ W) {
    __shared__ float Ws[2][KCF][E_];
    __shared__ float As2[2][KCF][132];
    __shared__ float K1s[BMF][NR];

    int tid = threadIdx.x;
    int t0  = blockIdx.x * BMF;
    int ks  = blockIdx.y;
    int k0  = ks * KQ;

#pragma unroll
    for (int j = 0; j < 4; j++) {
        int idx = tid + 128 * j;
        K1s[idx >> 3][idx & 7] = g_stats[(t0 + (idx >> 3)) * 12 + (idx & 7)];
    }
    __syncthreads();

    unsigned long long acc[8][4];
#pragma unroll
    for (int i = 0; i < 8; i++)
#pragma unroll
        for (int j = 0; j < 4; j++) acc[i][j] = 0ull;

    int tx = tid & 15, ty = tid >> 4;
    int tokA = tid >> 1, kA = (tid & 1) * 8;

    float4 wst[4];
    float4 bst[2];
    uchar4 cst[2];

    auto stage = [&](int kc) {
#pragma unroll
        for (int j = 0; j < 4; j++) {
            int p  = tid + 128 * j;
            int v  = p >> 5;
            int e4 = (p & 31) * 4;
            int gv = kc + v;
            wst[j] = (gv < V_) ? *(const float4*)&W[(size_t)gv * E_ + e4]
                               : make_float4(0.f, 0.f, 0.f, 0.f);
        }
        int gb = kc + kA;
        if (gb < V_) {
            size_t off = (size_t)(t0 + tokA) * VPAD + gb;
            bst[0] = *(const float4*)(g_base + off);
            bst[1] = *(const float4*)(g_base + off + 4);
            cst[0] = *(const uchar4*)(g_cls + off);
            cst[1] = *(const uchar4*)(g_cls + off + 4);
        } else {
            bst[0] = bst[1] = make_float4(0.f, 0.f, 0.f, 0.f);
            cst[0] = cst[1] = make_uchar4(0, 0, 0, 0);
        }
    };
    auto commit = [&](int buf) {
#pragma unroll
        for (int j = 0; j < 4; j++) {
            int p  = tid + 128 * j;
            int v  = p >> 5;
            int e4 = (p & 31) * 4;
            *(float4*)&Ws[buf][v][e4] = wst[j];
        }
#pragma unroll
        for (int h = 0; h < 2; h++) {
            float bb[4] = {bst[h].x, bst[h].y, bst[h].z, bst[h].w};
            unsigned char ccs[4] = {cst[h].x, cst[h].y, cst[h].z, cst[h].w};
#pragma unroll
            for (int j = 0; j < 4; j++) {
                float g = 0.f;
                int c = ccs[j];
                if (c) g = K1s[tokA][c - 1] * (__expf(bb[j]) - 1.f);
                *(float2*)&As2[buf][kA + 4 * h + j][2 * tokA] = make_float2(g, g);
            }
        }
    };

    stage(k0);
    commit(0);
    int buf = 0;

    for (int i = 0; i < NCHF; i++) {
        __syncthreads();
        if (i + 1 < NCHF) stage(k0 + (i + 1) * KCF);
#pragma unroll
        for (int kk = 0; kk < KCF; kk++) {
            ulonglong2 w01 = *(const ulonglong2*)&Ws[buf][kk][8 * tx];
            ulonglong2 w23 = *(const ulonglong2*)&Ws[buf][kk][8 * tx + 4];
            ulonglong2 a01 = *(const ulonglong2*)&As2[buf][kk][16 * ty];
            ulonglong2 a23 = *(const ulonglong2*)&As2[buf][kk][16 * ty + 4];
            ulonglong2 a45 = *(const ulonglong2*)&As2[buf][kk][16 * ty + 8];
            ulonglong2 a67 = *(const ulonglong2*)&As2[buf][kk][16 * ty + 12];
            unsigned long long a[8] = {a01.x, a01.y, a23.x, a23.y,
                                       a45.x, a45.y, a67.x, a67.y};
            unsigned long long w[4] = {w01.x, w01.y, w23.x, w23.y};
#pragma unroll
            for (int ii = 0; ii < 8; ii++)
#pragma unroll
                for (int jj = 0; jj < 4; jj++)
                    fma2(acc[ii][jj], a[ii], w[jj]);
        }
        if (i + 1 < NCHF) commit(buf ^ 1);
        buf ^= 1;
    }

    float* ps = g_psum[ks];
#pragma unroll
    for (int i = 0; i < 8; i++) {
        int t = t0 + 8 * ty + i;
        float2 p0 = *(float2*)&acc[i][0];
        float2 p1 = *(float2*)&acc[i][1];
        float2 p2 = *(float2*)&acc[i][2];
        float2 p3 = *(float2*)&acc[i][3];
        *(float4*)&ps[(size_t)t * E_ + 8 * tx]     = make_float4(p0.x, p0.y, p1.x, p1.y);
        *(float4*)&ps[(size_t)t * E_ + 8 * tx + 4] = make_float4(p2.x, p2.y, p3.x, p3.y);
    }
}

// ---------------- combine K-split partials + background term ----------------
__global__ void k_combine(float* __restrict__ out) {
    int i  = blockIdx.x * 256 + threadIdx.x;
    int t  = i >> 5;
    int c4 = (i & 31) * 4;
    size_t off = (size_t)t * E_ + c4;
    float  beta = g_stats[t * 12 + 8];
    float4 cs = *(const float4*)&g_colsum[c4];
    float4 o = make_float4(beta * cs.x, beta * cs.y, beta * cs.z, beta * cs.w);
#pragma unroll
    for (int r = 0; r < KSPLIT; r++) {
        float4 a = *(const float4*)&g_psum[r][off];
        o.x += a.x; o.y += a.y; o.z += a.z; o.w += a.w;
    }
    *(float4*)&out[off] = o;
}

// ---------------- launch ----------------
extern "C" void kernel_launch(void* const* d_in, const int* in_sizes, int n_in,
                              void* d_out, int out_size) {
    const int*   src  = (const int*)  d_in[0];
    const float* X    = (const float*)d_in[1];
    const float* W    = (const float*)d_in[2];
    const float* edge = (const float*)d_in[3];
    const int*   rel  = (const int*)  d_in[4];
    float* out = (float*)d_out;

    cudaFuncSetAttribute(k_base, cudaFuncAttributeMaxDynamicSharedMemorySize, SMEM_KB);

    k_colsum1<<<40, 128>>>(W);
    k_colsum2<<<1, 128>>>();

    dim3 gb((V_ + BV - 1) / BV, NTOK / BT);   // 79 x 32
    k_base<<<gb, 128, SMEM_KB>>>(src, X, W, edge, rel);

    k_stats<<<NTOK, 256>>>();

    k_final<<<dim3(NTOK / BMF, KSPLIT), 128>>>(W);  // 32 x 9 = 288 CTAs

    k_combine<<<256, 256>>>(out);
    (void)in_sizes; (void)n_in; (void)out_size;
}

// round 6
// speedup vs baseline: 3.0359x; 1.0378x over previous
#include <cuda_runtime.h>
#include <cstdint>

#define V_     10000
#define VPAD   10240
#define E_     128
#define NTOK   2048
#define NR     8

#define KSPLIT 18
#define KQ     576          // 18*576 = 10368 covers VPAD with guards

// ---------------- scratch (device globals; no allocations) ----------------
__device__ float         g_base[(size_t)NTOK * VPAD];   // q = exp(base)-1 (pad cols = 0)
__device__ unsigned char g_cls [(size_t)NTOK * VPAD];   // class 0..8; pad stays 0
__device__ float         g_colsum[E_];
__device__ float         g_part[40 * E_];
__device__ float         g_stats[NTOK * 12];             // K1[8], beta
__device__ float         g_psum[KSPLIT][(size_t)NTOK * E_];

__device__ __forceinline__ void fma2(unsigned long long& acc,
                                     unsigned long long a, unsigned long long b) {
    asm("fma.rn.f32x2 %0, %1, %2, %0;" : "+l"(acc) : "l"(a), "l"(b));
}
__device__ __forceinline__ uint32_t s2u(const void* p) {
    return (uint32_t)__cvta_generic_to_shared(p);
}
#define CP_ASYNC16(dst, src) \
    asm volatile("cp.async.cg.shared.global [%0], [%1], 16;\n" :: "r"(dst), "l"(src))
#define CP_COMMIT() asm volatile("cp.async.commit_group;\n" ::: "memory")
#define CP_WAIT0()  asm volatile("cp.async.wait_group 0;\n" ::: "memory")

// ---------------- column sums of W (deterministic 2-stage) ----------------
__global__ void k_colsum1(const float* __restrict__ W) {
    int b = blockIdx.x, col = threadIdx.x;
    float s = 0.f;
    int v0 = b * 250;
    for (int v = v0; v < v0 + 250; v++) s += W[v * E_ + col];
    g_part[b * E_ + col] = s;
}
__global__ void k_colsum2() {
    int col = threadIdx.x;
    float s = 0.f;
    for (int b = 0; b < 40; b++) s += g_part[b * E_ + col];
    g_colsum[col] = s;
}

// ---------------- base GEMM (f32x2, 8x8 tile, double-buffered) + classify ----------------
#define BT 64
#define BV 128
#define KCB 16

// dynamic smem layout (bytes)
#define XBUF_B   (KCB * 132 * 4)           // 8448
#define WBUF_B   (KCB * 132 * 4)           // 8448
#define OFF_XS2  0
#define OFF_WS   (2 * XBUF_B)              // 16896
#define OFF_REL  (OFF_WS + 2 * WBUF_B)     // 33792
#define OFF_EDGE (OFF_REL + 32768)         // 66560
#define OFF_SSM  (OFF_EDGE + 32768)        // 99328
#define SMEM_KB  (OFF_SSM + 256)           // 99584

__global__ __launch_bounds__(128) void k_base(
    const int*   __restrict__ src,
    const float* __restrict__ X,
    const float* __restrict__ W,
    const float* __restrict__ edge,
    const int*   __restrict__ rel)
{
    extern __shared__ char smraw[];
    float (*Xs2)[KCB][132] = (float(*)[KCB][132])(smraw + OFF_XS2);
    float (*Ws)[KCB][132]  = (float(*)[KCB][132])(smraw + OFF_WS);
    int*    rel_s  = (int*)  (smraw + OFF_REL);    // [64 tok][128 v]
    float*  edge_s = (float*)(smraw + OFF_EDGE);   // [64 tok][128 v]
    int*    ssm    = (int*)  (smraw + OFF_SSM);

    int tid  = threadIdx.x;
    int vblk = blockIdx.x * BV;
    int tblk = blockIdx.y * BT;
    if (tid < BT) ssm[tid] = src[tblk + tid];
    __syncthreads();

    // prefetch rel/edge tiles (64 tok x 128 v) via cp.async — hidden under GEMM
    uint32_t rel_su  = s2u(rel_s);
    uint32_t edge_su = s2u(edge_s);
#pragma unroll
    for (int j = 0; j < 16; j++) {
        int chunk = tid + 128 * j;          // 0..2047, 16B chunks
        int tok = chunk >> 5;
        int vloc = (chunk & 31) * 4;
        int v = vblk + vloc;
        if (v < V_) {
            long s = ssm[tok];
            CP_ASYNC16(rel_su  + chunk * 16, rel  + s * (long)V_ + v);
            CP_ASYNC16(edge_su + chunk * 16, edge + s * (long)V_ + v);
        }
    }
    CP_COMMIT();

    unsigned long long acc[8][4];
#pragma unroll
    for (int i = 0; i < 8; i++)
#pragma unroll
        for (int j = 0; j < 4; j++) acc[i][j] = 0ull;

    int tx = tid & 15;     // col group: 8*tx..8*tx+7
    int ty = tid >> 4;     // token group: 8*ty..8*ty+7
    int xtok = tid & 63, xkq = tid >> 6;
    int gvW  = vblk + tid;

    float4 xst[2], wst[4];
    auto stage = [&](int kc) {
#pragma unroll
        for (int j = 0; j < 2; j++) {
            int k4 = 4 * (xkq + 2 * j);
            xst[j] = *(const float4*)&X[(size_t)(tblk + xtok) * E_ + kc + k4];
        }
#pragma unroll
        for (int j = 0; j < 4; j++) {
            wst[j] = (gvW < V_) ? *(const float4*)&W[(size_t)gvW * E_ + kc + 4 * j]
                                : make_float4(0.f, 0.f, 0.f, 0.f);
        }
    };
    auto commit = [&](int buf) {
#pragma unroll
        for (int j = 0; j < 2; j++) {
            int k4 = 4 * (xkq + 2 * j);
            *(float2*)&Xs2[buf][k4 + 0][2 * xtok] = make_float2(xst[j].x, xst[j].x);
            *(float2*)&Xs2[buf][k4 + 1][2 * xtok] = make_float2(xst[j].y, xst[j].y);
            *(float2*)&Xs2[buf][k4 + 2][2 * xtok] = make_float2(xst[j].z, xst[j].z);
            *(float2*)&Xs2[buf][k4 + 3][2 * xtok] = make_float2(xst[j].w, xst[j].w);
        }
#pragma unroll
        for (int j = 0; j < 4; j++) {
            int k4 = 4 * j;
            Ws[buf][k4 + 0][tid] = wst[j].x;
            Ws[buf][k4 + 1][tid] = wst[j].y;
            Ws[buf][k4 + 2][tid] = wst[j].z;
            Ws[buf][k4 + 3][tid] = wst[j].w;
        }
    };

    stage(0);
    commit(0);
    int buf = 0;
#define NCHB (E_ / KCB)   // 8
    for (int ch = 0; ch < NCHB; ch++) {
        __syncthreads();
        if (ch + 1 < NCHB) stage((ch + 1) * KCB);
#pragma unroll
        for (int kk = 0; kk < KCB; kk++) {
            ulonglong2 w01 = *(const ulonglong2*)&Ws[buf][kk][8 * tx];
            ulonglong2 w23 = *(const ulonglong2*)&Ws[buf][kk][8 * tx + 4];
            ulonglong2 a01 = *(const ulonglong2*)&Xs2[buf][kk][16 * ty];
            ulonglong2 a23 = *(const ulonglong2*)&Xs2[buf][kk][16 * ty + 4];
            ulonglong2 a45 = *(const ulonglong2*)&Xs2[buf][kk][16 * ty + 8];
            ulonglong2 a67 = *(const ulonglong2*)&Xs2[buf][kk][16 * ty + 12];
            unsigned long long a[8] = {a01.x, a01.y, a23.x, a23.y,
                                       a45.x, a45.y, a67.x, a67.y};
            unsigned long long w[4] = {w01.x, w01.y, w23.x, w23.y};
#pragma unroll
            for (int i = 0; i < 8; i++)
#pragma unroll
                for (int j = 0; j < 4; j++)
                    fma2(acc[i][j], a[i], w[j]);
        }
        if (ch + 1 < NCHB) commit(buf ^ 1);
        buf ^= 1;
    }

    CP_WAIT0();
    __syncthreads();

    int v0 = vblk + 8 * tx;
#pragma unroll
    for (int i = 0; i < 8; i++) {
        int tl = 8 * ty + i;
        int t  = tblk + tl;
        float2 p0 = *(float2*)&acc[i][0];
        float2 p1 = *(float2*)&acc[i][1];
        float2 p2 = *(float2*)&acc[i][2];
        float2 p3 = *(float2*)&acc[i][3];
        // store q = exp(b) - 1  (pad region: b = 0 -> q = 0)
        float4 q0 = make_float4(__expf(p0.x) - 1.f, __expf(p0.y) - 1.f,
                                __expf(p1.x) - 1.f, __expf(p1.y) - 1.f);
        float4 q1 = make_float4(__expf(p2.x) - 1.f, __expf(p2.y) - 1.f,
                                __expf(p3.x) - 1.f, __expf(p3.y) - 1.f);
        *(float4*)&g_base[(size_t)t * VPAD + v0]     = q0;
        *(float4*)&g_base[(size_t)t * VPAD + v0 + 4] = q1;
        if (v0 < V_) {
#pragma unroll
            for (int h = 0; h < 2; h++) {
                int vloc = 8 * tx + 4 * h;
                int4   r4 = *(const int4*)  &rel_s [tl * 128 + vloc];
                float4 e4 = *(const float4*)&edge_s[tl * 128 + vloc];
                uchar4 c;
                c.x = (r4.x >= 1 && r4.x <= 8 && e4.x > 0.f) ? (unsigned char)r4.x : 0;
                c.y = (r4.y >= 1 && r4.y <= 8 && e4.y > 0.f) ? (unsigned char)r4.y : 0;
                c.z = (r4.z >= 1 && r4.z <= 8 && e4.z > 0.f) ? (unsigned char)r4.z : 0;
                c.w = (r4.w >= 1 && r4.w <= 8 && e4.w > 0.f) ? (unsigned char)r4.w : 0;
                *(uchar4*)&g_cls[(size_t)t * VPAD + v0 + 4 * h] = c;
            }
        }
    }
}

// ---------------- per-(t,r) stats from q: lane-private smem RMW, 2 chains ----------------
#define CSTRIDE 33

__global__ __launch_bounds__(256) void k_stats() {
    __shared__ float2 accs[2][8][9 * CSTRIDE];   // [copy][warp][class*33 + lane]
    __shared__ float  eArr[NR], dArr[NR], Bsh[8];

    int t   = blockIdx.x;
    int tid = threadIdx.x;
    int w   = tid >> 5, lane = tid & 31;

    for (int i = tid; i < 2 * 8 * 9 * CSTRIDE; i += 256)
        ((float2*)accs)[i] = make_float2(0.f, 0.f);
    __syncthreads();

    float B = 0.f;
    const float*         qRow   = g_base + (size_t)t * VPAD;
    const unsigned char* clsRow = g_cls  + (size_t)t * VPAD;

    for (int i = tid; i < V_ / 4; i += 256) {
        float4 q4 = *(const float4*)(qRow + 4 * i);
        uchar4 c4 = *(const uchar4*)(clsRow + 4 * i);
        float qs[4] = {q4.x, q4.y, q4.z, q4.w};
        int   cc[4] = {c4.x, c4.y, c4.z, c4.w};
#pragma unroll
        for (int j = 0; j < 4; j++) {
            float q = qs[j];
            float b = __logf(fmaxf(q + 1.f, 1e-38f));
            B += b;
            float2* p = &accs[j & 1][w][cc[j] * CSTRIDE + lane];
            float2 o = *p;
            o.x += q;
            o.y = fmaf(q, b, o.y);
            *p = o;
        }
    }
#pragma unroll
    for (int o = 16; o; o >>= 1) B += __shfl_xor_sync(0xFFFFFFFFu, B, o);
    if (lane == 0) Bsh[w] = B;
    __syncthreads();

    // class reduce: warp w handles class w+1, both copies
    {
        float2 s = make_float2(0.f, 0.f);
#pragma unroll
        for (int ww = 0; ww < 8; ww++) {
            float2 a0 = accs[0][ww][(w + 1) * CSTRIDE + lane];
            float2 a1 = accs[1][ww][(w + 1) * CSTRIDE + lane];
            s.x += a0.x + a1.x;
            s.y += a0.y + a1.y;
        }
#pragma unroll
        for (int o = 16; o; o >>= 1) {
            s.x += __shfl_xor_sync(0xFFFFFFFFu, s.x, o);
            s.y += __shfl_xor_sync(0xFFFFFFFFu, s.y, o);
        }
        if (lane == 0) { eArr[w] = s.x; dArr[w] = s.y; }
    }
    __syncthreads();

    if (tid == 0) {
        float Bt = 0.f;
#pragma unroll
        for (int k = 0; k < 8; k++) Bt += Bsh[k];
        float sc[NR], Zv[NR];
#pragma unroll
        for (int r = 0; r < NR; r++) {
            float Z = (float)V_ + eArr[r];
            Zv[r] = Z;
            sc[r] = (dArr[r] + Bt) / Z;
        }
        float mx = sc[0];
#pragma unroll
        for (int r = 1; r < NR; r++) mx = fmaxf(mx, sc[r]);
        float es[NR], ss = 0.f;
#pragma unroll
        for (int r = 0; r < NR; r++) { es[r] = __expf(sc[r] - mx); ss += es[r]; }
        float inv = 1.f / ss;
        float beta = 0.f;
        float* st = g_stats + t * 12;
#pragma unroll
        for (int r = 0; r < NR; r++) {
            float K1 = es[r] * inv / Zv[r];
            st[r] = K1;
            beta += K1;
        }
        st[8] = beta;
    }
}

// ---------------- final GEMM: gamma = K1[c]*q, 8x8 tile, double-buffered ----------------
#define BMF  64
#define KCF  16
#define NCHF (KQ / KCF)      // 36

__global__ __launch_bounds__(128) void k_final(const float* __restrict__ W) {
    __shared__ float Ws[2][KCF][E_];
    __shared__ float As2[2][KCF][132];
    __shared__ float K1s[BMF][NR];

    int tid = threadIdx.x;
    int t0  = blockIdx.x * BMF;
    int ks  = blockIdx.y;
    int k0  = ks * KQ;

#pragma unroll
    for (int j = 0; j < 4; j++) {
        int idx = tid + 128 * j;
        K1s[idx >> 3][idx & 7] = g_stats[(t0 + (idx >> 3)) * 12 + (idx & 7)];
    }
    __syncthreads();

    unsigned long long acc[8][4];
#pragma unroll
    for (int i = 0; i < 8; i++)
#pragma unroll
        for (int j = 0; j < 4; j++) acc[i][j] = 0ull;

    int tx = tid & 15, ty = tid >> 4;
    int tokA = tid >> 1, kA = (tid & 1) * 8;

    float4 wst[4];
    float4 bst[2];
    uchar4 cst[2];

    auto stage = [&](int kc) {
#pragma unroll
        for (int j = 0; j < 4; j++) {
            int p  = tid + 128 * j;
            int v  = p >> 5;
            int e4 = (p & 31) * 4;
            int gv = kc + v;
            wst[j] = (gv < V_) ? *(const float4*)&W[(size_t)gv * E_ + e4]
                               : make_float4(0.f, 0.f, 0.f, 0.f);
        }
        int gb = kc + kA;
        if (gb < V_) {
            size_t off = (size_t)(t0 + tokA) * VPAD + gb;
            bst[0] = *(const float4*)(g_base + off);
            bst[1] = *(const float4*)(g_base + off + 4);
            cst[0] = *(const uchar4*)(g_cls + off);
            cst[1] = *(const uchar4*)(g_cls + off + 4);
        } else {
            bst[0] = bst[1] = make_float4(0.f, 0.f, 0.f, 0.f);
            cst[0] = cst[1] = make_uchar4(0, 0, 0, 0);
        }
    };
    auto commit = [&](int buf) {
#pragma unroll
        for (int j = 0; j < 4; j++) {
            int p  = tid + 128 * j;
            int v  = p >> 5;
            int e4 = (p & 31) * 4;
            *(float4*)&Ws[buf][v][e4] = wst[j];
        }
#pragma unroll
        for (int h = 0; h < 2; h++) {
            float qq[4] = {bst[h].x, bst[h].y, bst[h].z, bst[h].w};
            unsigned char ccs[4] = {cst[h].x, cst[h].y, cst[h].z, cst[h].w};
#pragma unroll
            for (int j = 0; j < 4; j++) {
                float g = 0.f;
                int c = ccs[j];
                if (c) g = K1s[tokA][c - 1] * qq[j];
                *(float2*)&As2[buf][kA + 4 * h + j][2 * tokA] = make_float2(g, g);
            }
        }
    };

    stage(k0);
    commit(0);
    int buf = 0;

    for (int i = 0; i < NCHF; i++) {
        __syncthreads();
        if (i + 1 < NCHF) stage(k0 + (i + 1) * KCF);
#pragma unroll
        for (int kk = 0; kk < KCF; kk++) {
            ulonglong2 w01 = *(const ulonglong2*)&Ws[buf][kk][8 * tx];
            ulonglong2 w23 = *(const ulonglong2*)&Ws[buf][kk][8 * tx + 4];
            ulonglong2 a01 = *(const ulonglong2*)&As2[buf][kk][16 * ty];
            ulonglong2 a23 = *(const ulonglong2*)&As2[buf][kk][16 * ty + 4];
            ulonglong2 a45 = *(const ulonglong2*)&As2[buf][kk][16 * ty + 8];
            ulonglong2 a67 = *(const ulonglong2*)&As2[buf][kk][16 * ty + 12];
            unsigned long long a[8] = {a01.x, a01.y, a23.x, a23.y,
                                       a45.x, a45.y, a67.x, a67.y};
            unsigned long long w[4] = {w01.x, w01.y, w23.x, w23.y};
#pragma unroll
            for (int ii = 0; ii < 8; ii++)
#pragma unroll
                for (int jj = 0; jj < 4; jj++)
                    fma2(acc[ii][jj], a[ii], w[jj]);
        }
        if (i + 1 < NCHF) commit(buf ^ 1);
        buf ^= 1;
    }

    float* ps = g_psum[ks];
#pragma unroll
    for (int i = 0; i < 8; i++) {
        int t = t0 + 8 * ty + i;
        float2 p0 = *(float2*)&acc[i][0];
        float2 p1 = *(float2*)&acc[i][1];
        float2 p2 = *(float2*)&acc[i][2];
        float2 p3 = *(float2*)&acc[i][3];
        *(float4*)&ps[(size_t)t * E_ + 8 * tx]     = make_float4(p0.x, p0.y, p1.x, p1.y);
        *(float4*)&ps[(size_t)t * E_ + 8 * tx + 4] = make_float4(p2.x, p2.y, p3.x, p3.y);
    }
}

// ---------------- combine K-split partials + background term ----------------
__global__ void k_combine(float* __restrict__ out) {
    int i  = blockIdx.x * 256 + threadIdx.x;
    int t  = i >> 5;
    int c4 = (i & 31) * 4;
    size_t off = (size_t)t * E_ + c4;
    float  beta = g_stats[t * 12 + 8];
    float4 cs = *(const float4*)&g_colsum[c4];
    float4 o = make_float4(beta * cs.x, beta * cs.y, beta * cs.z, beta * cs.w);
#pragma unroll
    for (int r = 0; r < KSPLIT; r++) {
        float4 a = *(const float4*)&g_psum[r][off];
        o.x += a.x; o.y += a.y; o.z += a.z; o.w += a.w;
    }
    *(float4*)&out[off] = o;
}

// ---------------- launch ----------------
extern "C" void kernel_launch(void* const* d_in, const int* in_sizes, int n_in,
                              void* d_out, int out_size) {
    const int*   src  = (const int*)  d_in[0];
    const float* X    = (const float*)d_in[1];
    const float* W    = (const float*)d_in[2];
    const float* edge = (const float*)d_in[3];
    const int*   rel  = (const int*)  d_in[4];
    float* out = (float*)d_out;

    cudaFuncSetAttribute(k_base, cudaFuncAttributeMaxDynamicSharedMemorySize, SMEM_KB);

    k_colsum1<<<40, 128>>>(W);
    k_colsum2<<<1, 128>>>();

    dim3 gb((V_ + BV - 1) / BV, NTOK / BT);   // 79 x 32
    k_base<<<gb, 128, SMEM_KB>>>(src, X, W, edge, rel);

    k_stats<<<NTOK, 256>>>();

    k_final<<<dim3(NTOK / BMF, KSPLIT), 128>>>(W);  // 32 x 18 = 576 CTAs

    k_combine<<<256, 256>>>(out);
    (void)in_sizes; (void)n_in; (void)out_size;
}